// round 6
// baseline (speedup 1.0000x reference)
#include <cuda_runtime.h>
#include <math.h>

#define B 64
#define S 512
#define H 768
#define K 64

// Scratch
__device__ float g_scores[3 * B * K];
__device__ float g_pooled[3 * B * H];

// ---------------------------------------------------------------------------
// K1: raw scores[j] = dot(G0, Gj). grid (B, 3, 4), block 256 (8 warps).
// Each warp computes 2 j's with all loads in flight together (MLP 12).
// Block (0,0,0) also initializes out[] with classifier biases.
// ---------------------------------------------------------------------------
__global__ void score_kernel(const float* __restrict__ seq,
                             const int* __restrict__ idx0,
                             const int* __restrict__ idx1,
                             const int* __restrict__ idx2,
                             const float* __restrict__ bc0,
                             const float* __restrict__ bc1,
                             const float* __restrict__ bc2,
                             float* __restrict__ out) {
    int b  = blockIdx.x;
    int t  = blockIdx.y;
    int jt = blockIdx.z;           // 16 j's per block
    const int* idxp = (t == 0) ? idx0 : (t == 1) ? idx1 : idx2;

    __shared__ int sidx[16];
    __shared__ int si0;

    int tid  = threadIdx.x;
    int wid  = tid >> 5;
    int lane = tid & 31;

    // bias init (layout: rel 64x9 | nov 64x3 | dir 64x3)
    if (b == 0 && t == 0 && jt == 0) {
        for (int i = tid; i < 960; i += 256) {
            float v;
            if (i < 576)      v = bc0[i % 9];
            else if (i < 768) v = bc1[(i - 576) % 3];
            else              v = bc2[(i - 768) % 3];
            out[i] = v;
        }
    }

    if (tid < 16) sidx[tid] = idxp[b * K + jt * 16 + tid];
    if (tid == 16) si0 = idxp[b * K];
    __syncthreads();

    const float* seqb = seq + (size_t)b * S * H;

    float4 g0v[6];
    const float4* r0 = (const float4*)(seqb + (size_t)si0 * H);
    #pragma unroll
    for (int i = 0; i < 6; i++) g0v[i] = r0[lane + 32 * i];

    const float4* ga = (const float4*)(seqb + (size_t)sidx[wid] * H);
    const float4* gb = (const float4*)(seqb + (size_t)sidx[wid + 8] * H);

    float4 av[6], bv[6];
    #pragma unroll
    for (int i = 0; i < 6; i++) { av[i] = ga[lane + 32 * i]; bv[i] = gb[lane + 32 * i]; }

    float sa = 0.f, sb = 0.f;
    #pragma unroll
    for (int i = 0; i < 6; i++) {
        sa += g0v[i].x * av[i].x + g0v[i].y * av[i].y
            + g0v[i].z * av[i].z + g0v[i].w * av[i].w;
        sb += g0v[i].x * bv[i].x + g0v[i].y * bv[i].y
            + g0v[i].z * bv[i].z + g0v[i].w * bv[i].w;
    }
    #pragma unroll
    for (int o = 16; o; o >>= 1) {
        sa += __shfl_xor_sync(0xffffffffu, sa, o);
        sb += __shfl_xor_sync(0xffffffffu, sb, o);
    }
    if (lane == 0) {
        float* dst = &g_scores[((size_t)t * B + b) * K + jt * 16];
        dst[wid]     = sa;
        dst[wid + 8] = sb;
    }
}

// ---------------------------------------------------------------------------
// K2: softmax + weighted sum. grid (B, 3, 4 htiles of 192), block 192.
// ---------------------------------------------------------------------------
__global__ void pool_kernel(const float* __restrict__ seq,
                            const int* __restrict__ idx0, const int* __restrict__ len0,
                            const int* __restrict__ idx1, const int* __restrict__ len1,
                            const int* __restrict__ idx2, const int* __restrict__ len2) {
    int b  = blockIdx.x;
    int t  = blockIdx.y;
    int h0 = blockIdx.z * 192;
    const int* idxp = (t == 0) ? idx0 : (t == 1) ? idx1 : idx2;
    const int* lenp = (t == 0) ? len0 : (t == 1) ? len1 : len2;

    __shared__ float prob[K];
    __shared__ int   sidx[K];

    int tid  = threadIdx.x;
    int lane = tid & 31;
    int len  = lenp[b];

    if (tid < K) sidx[tid] = idxp[b * K + tid];

    if (tid < 32) {
        const float* sc = &g_scores[((size_t)t * B + b) * K];
        float sa = (lane      < len) ? sc[lane]      : -1e30f;
        float sb = (lane + 32 < len) ? sc[lane + 32] : -1e30f;
        float m = fmaxf(sa, sb);
        #pragma unroll
        for (int o = 16; o; o >>= 1) m = fmaxf(m, __shfl_xor_sync(0xffffffffu, m, o));
        float ea = (lane      < len) ? expf(sa - m) : 0.f;
        float eb = (lane + 32 < len) ? expf(sb - m) : 0.f;
        float sum = ea + eb;
        #pragma unroll
        for (int o = 16; o; o >>= 1) sum += __shfl_xor_sync(0xffffffffu, sum, o);
        float inv = (sum > 0.f) ? (1.0f / sum) : 0.f;
        prob[lane]      = ea * inv;
        prob[lane + 32] = eb * inv;
    }
    __syncthreads();

    const float* base = seq + (size_t)b * S * H + h0 + tid;
    float acc = 0.f;
    #pragma unroll 16
    for (int j = 0; j < K; j++) {
        acc += prob[j] * base[(size_t)sidx[j] * H];
    }
    if (len == 0) acc = base[0];
    g_pooled[((size_t)t * B + b) * H + h0 + tid] = acc;
}

// ---------------------------------------------------------------------------
// K3: h = tanh(P @ Wd^T + bd) + fused classifier.
// grid (12 rtiles of 64, 4 btiles of 16, 3), block 128 (4 warps).
// Thread tile: rows {m, m+16, m+32, m+48} (m = lane%16) x 2 batches.
// ---------------------------------------------------------------------------
__global__ void dense_kernel(const float* __restrict__ Wd0, const float* __restrict__ bd0,
                             const float* __restrict__ Wd1, const float* __restrict__ bd1,
                             const float* __restrict__ Wd2, const float* __restrict__ bd2,
                             const float* __restrict__ Wc0,
                             const float* __restrict__ Wc1,
                             const float* __restrict__ Wc2,
                             float* __restrict__ out) {
    int t = blockIdx.z;
    const float* Wd = (t == 0) ? Wd0 : (t == 1) ? Wd1 : Wd2;
    const float* bd = (t == 0) ? bd0 : (t == 1) ? bd1 : bd2;
    const float* Wc = (t == 0) ? Wc0 : (t == 1) ? Wc1 : Wc2;
    int nlab   = (t == 0) ? 9 : 3;
    int outoff = (t == 0) ? 0 : (t == 1) ? B * 9 : B * 9 + B * 3;

    int r0 = blockIdx.x * 64;
    int b0 = blockIdx.y * 16;

    __shared__ float Ws[64][33];   // [r][kk]
    __shared__ float Pt[32][18];   // [kk][bb]
    __shared__ float Hs[16][65];   // h tile [batch][row 0..63], padded

    int tid  = threadIdx.x;
    int w    = tid >> 5;          // warp 0..3
    int lane = tid & 31;
    int m    = lane & 15;         // row base
    int hh   = lane >> 4;         // 0/1 -> batch subgroup
    int bbase = 4 * w + 2 * hh;   // batches bbase, bbase+1

    const float* P = g_pooled + (size_t)t * B * H;

    // staging decomposition:
    //  W: 512 float4s, 4/thread: f4 id = tid + 128q -> r = id%64, c4 = id/64
    //  P: 512 floats,  4/thread: id = tid + 128q -> kk = id%32, bb = id/32
    float4 wreg[4];
    float  preg[4];
    {
        #pragma unroll
        for (int q = 0; q < 4; q++) {
            int id = tid + 128 * q;
            int r  = id & 63, c4 = id >> 6;
            wreg[q] = *(const float4*)&Wd[(size_t)(r0 + r) * H + 4 * c4];
            int kk = id & 31, bb = id >> 5;
            preg[q] = P[(size_t)(b0 + bb) * H + kk];
        }
    }

    float acc[4][2] = {{0,0},{0,0},{0,0},{0,0}};   // [row i][batch u]

    for (int k0 = 0; k0 < H; k0 += 32) {
        // commit prefetched tile to smem
        #pragma unroll
        for (int q = 0; q < 4; q++) {
            int id = tid + 128 * q;
            int r  = id & 63, c4 = id >> 6;
            Ws[r][4 * c4 + 0] = wreg[q].x;
            Ws[r][4 * c4 + 1] = wreg[q].y;
            Ws[r][4 * c4 + 2] = wreg[q].z;
            Ws[r][4 * c4 + 3] = wreg[q].w;
            int kk = id & 31, bb = id >> 5;
            Pt[kk][bb] = preg[q];
        }
        __syncthreads();

        // prefetch next tile
        if (k0 + 32 < H) {
            #pragma unroll
            for (int q = 0; q < 4; q++) {
                int id = tid + 128 * q;
                int r  = id & 63, c4 = id >> 6;
                wreg[q] = *(const float4*)&Wd[(size_t)(r0 + r) * H + (k0 + 32) + 4 * c4];
                int kk = id & 31, bb = id >> 5;
                preg[q] = P[(size_t)(b0 + bb) * H + (k0 + 32) + kk];
            }
        }

        #pragma unroll
        for (int kk = 0; kk < 32; kk++) {
            float2 pv = *(const float2*)&Pt[kk][bbase];
            float w0 = Ws[m     ][kk];
            float w1 = Ws[m + 16][kk];
            float w2 = Ws[m + 32][kk];
            float w3 = Ws[m + 48][kk];
            acc[0][0] += w0 * pv.x;  acc[0][1] += w0 * pv.y;
            acc[1][0] += w1 * pv.x;  acc[1][1] += w1 * pv.y;
            acc[2][0] += w2 * pv.x;  acc[2][1] += w2 * pv.y;
            acc[3][0] += w3 * pv.x;  acc[3][1] += w3 * pv.y;
        }
        __syncthreads();
    }

    // epilogue: tanh + bias -> Hs
    #pragma unroll
    for (int i = 0; i < 4; i++) {
        int r = m + 16 * i;
        float bdr = __ldg(&bd[r0 + r]);
        Hs[bbase    ][r] = tanhf(acc[i][0] + bdr);
        Hs[bbase + 1][r] = tanhf(acc[i][1] + bdr);
    }
    __syncthreads();

    // fused classifier: warp w handles batches 4w..4w+3
    #pragma unroll
    for (int bb = 0; bb < 4; bb++) {
        int bl = 4 * w + bb;
        float h0v = Hs[bl][lane];
        float h1v = Hs[bl][lane + 32];
        for (int l = 0; l < nlab; l++) {
            const float* wr = Wc + (size_t)l * H + r0;
            float s = h0v * __ldg(wr + lane) + h1v * __ldg(wr + lane + 32);
            #pragma unroll
            for (int o = 16; o; o >>= 1) s += __shfl_xor_sync(0xffffffffu, s, o);
            if (lane == 0)
                atomicAdd(&out[outoff + (b0 + bl) * nlab + l], s);
        }
    }
}

// ---------------------------------------------------------------------------
extern "C" void kernel_launch(void* const* d_in, const int* in_sizes, int n_in,
                              void* d_out, int out_size) {
    const float* seq      = (const float*)d_in[0];
    const int*   rel_idx  = (const int*)d_in[1];
    const int*   rel_len  = (const int*)d_in[2];
    const int*   nov_idx  = (const int*)d_in[3];
    const int*   nov_len  = (const int*)d_in[4];
    const int*   dir_idx  = (const int*)d_in[5];
    const int*   dir_len  = (const int*)d_in[6];
    const float* rel_dW   = (const float*)d_in[7];
    const float* rel_db   = (const float*)d_in[8];
    const float* rel_cW   = (const float*)d_in[9];
    const float* rel_cb   = (const float*)d_in[10];
    const float* nov_dW   = (const float*)d_in[11];
    const float* nov_db   = (const float*)d_in[12];
    const float* nov_cW   = (const float*)d_in[13];
    const float* nov_cb   = (const float*)d_in[14];
    const float* dir_dW   = (const float*)d_in[15];
    const float* dir_db   = (const float*)d_in[16];
    const float* dir_cW   = (const float*)d_in[17];
    const float* dir_cb   = (const float*)d_in[18];
    float* out = (float*)d_out;

    score_kernel<<<dim3(B, 3, 4), 256>>>(seq, rel_idx, nov_idx, dir_idx,
                                         rel_cb, nov_cb, dir_cb, out);
    pool_kernel<<<dim3(B, 3, 4), 192>>>(seq, rel_idx, rel_len, nov_idx, nov_len,
                                        dir_idx, dir_len);
    dense_kernel<<<dim3(12, 4, 3), 128>>>(rel_dW, rel_db, nov_dW, nov_db,
                                          dir_dW, dir_db,
                                          rel_cW, nov_cW, dir_cW, out);
}

// round 7
// speedup vs baseline: 1.2434x; 1.2434x over previous
#include <cuda_runtime.h>
#include <math.h>

#define B 64
#define S 512
#define H 768
#define K 64

// Scratch
__device__ float g_scores[3 * B * K];
__device__ float g_pooled[3 * B * H];

// ---------------------------------------------------------------------------
// K1: raw scores[j] = dot(G0, Gj), j < len only. grid (B, 3, 4), block 256.
// Each warp computes up to 2 j's with all loads in flight (MLP 12).
// Block (0,0,0) also initializes out[] with classifier biases.
// ---------------------------------------------------------------------------
__global__ void score_kernel(const float* __restrict__ seq,
                             const int* __restrict__ idx0, const int* __restrict__ len0,
                             const int* __restrict__ idx1, const int* __restrict__ len1,
                             const int* __restrict__ idx2, const int* __restrict__ len2,
                             const float* __restrict__ bc0,
                             const float* __restrict__ bc1,
                             const float* __restrict__ bc2,
                             float* __restrict__ out) {
    int b  = blockIdx.x;
    int t  = blockIdx.y;
    int jt = blockIdx.z;           // 16 j's per block
    const int* idxp = (t == 0) ? idx0 : (t == 1) ? idx1 : idx2;
    const int* lenp = (t == 0) ? len0 : (t == 1) ? len1 : len2;

    __shared__ int sidx[16];
    __shared__ int si0;

    int tid  = threadIdx.x;
    int wid  = tid >> 5;
    int lane = tid & 31;

    // bias init (layout: rel 64x9 | nov 64x3 | dir 64x3)
    if (b == 0 && t == 0 && jt == 0) {
        for (int i = tid; i < 960; i += 256) {
            float v;
            if (i < 576)      v = bc0[i % 9];
            else if (i < 768) v = bc1[(i - 576) % 3];
            else              v = bc2[(i - 768) % 3];
            out[i] = v;
        }
    }

    int len = lenp[b];
    int j0  = jt * 16;
    if (j0 >= len) return;          // block-uniform early out (bias done above)

    if (tid < 16) sidx[tid] = idxp[b * K + j0 + tid];
    if (tid == 16) si0 = idxp[b * K];
    __syncthreads();

    const float* seqb = seq + (size_t)b * S * H;

    float4 g0v[6];
    const float4* r0 = (const float4*)(seqb + (size_t)si0 * H);
    #pragma unroll
    for (int i = 0; i < 6; i++) g0v[i] = r0[lane + 32 * i];

    bool doa = (j0 + wid)     < len;
    bool dob = (j0 + wid + 8) < len;
    // masked rows alias row sidx[0] (valid memory, result discarded)
    const float4* ga = (const float4*)(seqb + (size_t)sidx[doa ? wid : 0] * H);
    const float4* gb = (const float4*)(seqb + (size_t)sidx[dob ? wid + 8 : 0] * H);

    if (!doa) return;  // warp-uniform; if a is masked, b is too

    float4 av[6], bv[6];
    if (dob) {
        #pragma unroll
        for (int i = 0; i < 6; i++) { av[i] = ga[lane + 32 * i]; bv[i] = gb[lane + 32 * i]; }
    } else {
        #pragma unroll
        for (int i = 0; i < 6; i++) { av[i] = ga[lane + 32 * i]; bv[i] = make_float4(0,0,0,0); }
    }

    float sa = 0.f, sb = 0.f;
    #pragma unroll
    for (int i = 0; i < 6; i++) {
        sa += g0v[i].x * av[i].x + g0v[i].y * av[i].y
            + g0v[i].z * av[i].z + g0v[i].w * av[i].w;
        sb += g0v[i].x * bv[i].x + g0v[i].y * bv[i].y
            + g0v[i].z * bv[i].z + g0v[i].w * bv[i].w;
    }
    #pragma unroll
    for (int o = 16; o; o >>= 1) {
        sa += __shfl_xor_sync(0xffffffffu, sa, o);
        sb += __shfl_xor_sync(0xffffffffu, sb, o);
    }
    if (lane == 0) {
        float* dst = &g_scores[((size_t)t * B + b) * K + j0];
        dst[wid] = sa;
        if (dob) dst[wid + 8] = sb;
    }
}

// ---------------------------------------------------------------------------
// K2: softmax + weighted sum (j < len). grid (B, 3, 4 htiles of 192), block 192.
// ---------------------------------------------------------------------------
__global__ void pool_kernel(const float* __restrict__ seq,
                            const int* __restrict__ idx0, const int* __restrict__ len0,
                            const int* __restrict__ idx1, const int* __restrict__ len1,
                            const int* __restrict__ idx2, const int* __restrict__ len2) {
    int b  = blockIdx.x;
    int t  = blockIdx.y;
    int h0 = blockIdx.z * 192;
    const int* idxp = (t == 0) ? idx0 : (t == 1) ? idx1 : idx2;
    const int* lenp = (t == 0) ? len0 : (t == 1) ? len1 : len2;

    __shared__ float prob[K];
    __shared__ int   sidx[K];

    int tid  = threadIdx.x;
    int lane = tid & 31;
    int len  = lenp[b];

    if (tid < K) sidx[tid] = idxp[b * K + tid];

    if (tid < 32) {
        const float* sc = &g_scores[((size_t)t * B + b) * K];
        float sa = (lane      < len) ? sc[lane]      : -1e30f;
        float sb = (lane + 32 < len) ? sc[lane + 32] : -1e30f;
        float m = fmaxf(sa, sb);
        #pragma unroll
        for (int o = 16; o; o >>= 1) m = fmaxf(m, __shfl_xor_sync(0xffffffffu, m, o));
        float ea = (lane      < len) ? expf(sa - m) : 0.f;
        float eb = (lane + 32 < len) ? expf(sb - m) : 0.f;
        float sum = ea + eb;
        #pragma unroll
        for (int o = 16; o; o >>= 1) sum += __shfl_xor_sync(0xffffffffu, sum, o);
        float inv = (sum > 0.f) ? (1.0f / sum) : 0.f;
        prob[lane]      = ea * inv;
        prob[lane + 32] = eb * inv;
    }
    __syncthreads();

    const float* base = seq + (size_t)b * S * H + h0 + tid;
    float acc = 0.f;
    #pragma unroll 16
    for (int j = 0; j < len; j++) {
        acc += prob[j] * base[(size_t)sidx[j] * H];
    }
    if (len == 0) acc = base[0];
    g_pooled[((size_t)t * B + b) * H + h0 + tid] = acc;
}

// ---------------------------------------------------------------------------
// K3: h = tanh(P @ Wd^T + bd) tile + fused classifier (R4 proven version).
// grid (12 rtiles of 64, 4 btiles of 16, 3), block 256.
// Thread GEMM tile: rows {2tx, 2tx+1} x batches {2ty, 2ty+1}.
// ---------------------------------------------------------------------------
__global__ void dense_kernel(const float* __restrict__ Wd0, const float* __restrict__ bd0,
                             const float* __restrict__ Wd1, const float* __restrict__ bd1,
                             const float* __restrict__ Wd2, const float* __restrict__ bd2,
                             const float* __restrict__ Wc0,
                             const float* __restrict__ Wc1,
                             const float* __restrict__ Wc2,
                             float* __restrict__ out) {
    int t = blockIdx.z;
    const float* Wd = (t == 0) ? Wd0 : (t == 1) ? Wd1 : Wd2;
    const float* bd = (t == 0) ? bd0 : (t == 1) ? bd1 : bd2;
    const float* Wc = (t == 0) ? Wc0 : (t == 1) ? Wc1 : Wc2;
    int nlab   = (t == 0) ? 9 : 3;
    int outoff = (t == 0) ? 0 : (t == 1) ? B * 9 : B * 9 + B * 3;

    int r0 = blockIdx.x * 64;
    int b0 = blockIdx.y * 16;

    __shared__ float Ws[32][66];   // Ws[kk][r]
    __shared__ float Ps[16][32];   // Ps[bb][kk]
    __shared__ float Hs[16][66];   // h tile, batch-major

    int tid = threadIdx.x;
    int tx = tid & 31;    // rows 2tx, 2tx+1
    int ty = tid >> 5;    // batches 2ty, 2ty+1

    float acc[2][2] = {{0.f, 0.f}, {0.f, 0.f}};   // [batch][row]

    const float* P = g_pooled + (size_t)t * B * H;

    for (int k0 = 0; k0 < H; k0 += 32) {
        #pragma unroll
        for (int i = 0; i < 8; i++) {
            int id = tid + 256 * i;
            int r  = id >> 5;
            int kk = id & 31;
            Ws[kk][r] = Wd[(size_t)(r0 + r) * H + (k0 + kk)];
        }
        #pragma unroll
        for (int i = 0; i < 2; i++) {
            int id = tid + 256 * i;
            int bb = id >> 5;
            int kk = id & 31;
            Ps[bb][kk] = P[(size_t)(b0 + bb) * H + (k0 + kk)];
        }
        __syncthreads();

        #pragma unroll
        for (int kk = 0; kk < 32; kk++) {
            float w0 = Ws[kk][2 * tx];
            float w1 = Ws[kk][2 * tx + 1];
            float p0 = Ps[2 * ty][kk];
            float p1 = Ps[2 * ty + 1][kk];
            acc[0][0] += p0 * w0;  acc[0][1] += p0 * w1;
            acc[1][0] += p1 * w0;  acc[1][1] += p1 * w1;
        }
        __syncthreads();
    }

    int r = 2 * tx;
    float bdr0 = bd[r0 + r];
    float bdr1 = bd[r0 + r + 1];
    #pragma unroll
    for (int bb = 0; bb < 2; bb++) {
        Hs[2 * ty + bb][r]     = tanhf(acc[bb][0] + bdr0);
        Hs[2 * ty + bb][r + 1] = tanhf(acc[bb][1] + bdr1);
    }
    __syncthreads();

    // Fused classifier: warp ty handles batches 2ty, 2ty+1.
    int lane = tx;
    #pragma unroll
    for (int bb = 0; bb < 2; bb++) {
        int bl = 2 * ty + bb;
        float h0v = Hs[bl][lane];
        float h1v = Hs[bl][lane + 32];
        for (int l = 0; l < nlab; l++) {
            const float* wr = Wc + (size_t)l * H + r0;
            float s = h0v * __ldg(wr + lane) + h1v * __ldg(wr + lane + 32);
            #pragma unroll
            for (int o = 16; o; o >>= 1) s += __shfl_xor_sync(0xffffffffu, s, o);
            if (lane == 0)
                atomicAdd(&out[outoff + (b0 + bl) * nlab + l], s);
        }
    }
}

// ---------------------------------------------------------------------------
extern "C" void kernel_launch(void* const* d_in, const int* in_sizes, int n_in,
                              void* d_out, int out_size) {
    const float* seq      = (const float*)d_in[0];
    const int*   rel_idx  = (const int*)d_in[1];
    const int*   rel_len  = (const int*)d_in[2];
    const int*   nov_idx  = (const int*)d_in[3];
    const int*   nov_len  = (const int*)d_in[4];
    const int*   dir_idx  = (const int*)d_in[5];
    const int*   dir_len  = (const int*)d_in[6];
    const float* rel_dW   = (const float*)d_in[7];
    const float* rel_db   = (const float*)d_in[8];
    const float* rel_cW   = (const float*)d_in[9];
    const float* rel_cb   = (const float*)d_in[10];
    const float* nov_dW   = (const float*)d_in[11];
    const float* nov_db   = (const float*)d_in[12];
    const float* nov_cW   = (const float*)d_in[13];
    const float* nov_cb   = (const float*)d_in[14];
    const float* dir_dW   = (const float*)d_in[15];
    const float* dir_db   = (const float*)d_in[16];
    const float* dir_cW   = (const float*)d_in[17];
    const float* dir_cb   = (const float*)d_in[18];
    float* out = (float*)d_out;

    score_kernel<<<dim3(B, 3, 4), 256>>>(seq, rel_idx, rel_len, nov_idx, nov_len,
                                         dir_idx, dir_len,
                                         rel_cb, nov_cb, dir_cb, out);
    pool_kernel<<<dim3(B, 3, 4), 192>>>(seq, rel_idx, rel_len, nov_idx, nov_len,
                                        dir_idx, dir_len);
    dense_kernel<<<dim3(12, 4, 3), 256>>>(rel_dW, rel_db, nov_dW, nov_db,
                                          dir_dW, dir_db,
                                          rel_cW, nov_cW, dir_cW, out);
}